// round 6
// baseline (speedup 1.0000x reference)
#include <cuda_runtime.h>
#include <cuda_bf16.h>
#include <math.h>
#include <stdint.h>

// ---------------- static problem config ----------------
#define NTOK   8192
#define HDIM   1024
#define CH     2048
#define CTXD   64
#define POSD   32
#define DGDIM  1120
#define HIDDIM 3072
#define NEXP   8
#define NKENT  16384
#define CAP    2048
#define BATCH  4
#define SEQ    2048

// expanded-K (bf16x2 split, 3 products) widths
#define KP1   (3*HDIM)    // 3072
#define KP2   (3*CH)      // 6144
#define KP45  (3*DGDIM)   // 3360
#define KP6   (3*HIDDIM)  // 9216
#define NPAD2 128
#define NPAD6 1152

// output layout (flat float32, tuple order)
#define OFF_IDX   0
#define OFF_SCORE 16384
#define OFF_MASK  32768
#define OFF_POS   49152
#define OFF_OVER  65536
#define OFF_CNT   73728
#define OFF_AUX   73736
#define OFF_NEXT  73737

// ---------------- scratch (device globals, no allocation) ----------------
__device__ float g_hidden[NTOK * CH];
__device__ float g_ctx[NTOK * CTXD];
__device__ float g_gi[NTOK * DGDIM];
__device__ float g_s1[NTOK * HIDDIM];
__device__ float g_h1[NTOK * HIDDIM];
__device__ float g_h[NTOK * DGDIM];
__device__ float g_scores[NTOK * NEXP];
__device__ unsigned long long g_keys[NKENT];
__device__ int g_expert_flat[NKENT];
__device__ unsigned char g_assigned[NKENT];
__device__ int g_cnt[NEXP];

__device__ __align__(256) __nv_bfloat16 g_ax  [NTOK * KP1];
__device__ __align__(256) __nv_bfloat16 g_ah  [NTOK * KP2];
__device__ __align__(256) __nv_bfloat16 g_agi [NTOK * KP45];
__device__ __align__(256) __nv_bfloat16 g_ah1 [NTOK * KP6];
__device__ __align__(256) __nv_bfloat16 g_wc1t[CH    * KP1];
__device__ __align__(256) __nv_bfloat16 g_wc2t[NPAD2 * KP2];
__device__ __align__(256) __nv_bfloat16 g_w1t [HIDDIM* KP45];
__device__ __align__(256) __nv_bfloat16 g_w3t [HIDDIM* KP45];
__device__ __align__(256) __nv_bfloat16 g_w2t [NPAD6 * KP6];

// ---------------- helpers ----------------
__device__ __forceinline__ uint32_t smem_u32(const void* p) {
    uint32_t a;
    asm("{ .reg .u64 t; cvta.to.shared.u64 t, %1; cvt.u32.u64 %0, t; }"
        : "=r"(a) : "l"(p));
    return a;
}
#define CPA16(sa, gp) asm volatile("cp.async.cg.shared.global [%0], [%1], 16;" ::"r"(sa),"l"(gp):"memory")
#define CPA_COMMIT()  asm volatile("cp.async.commit_group;" ::: "memory")
#define CPA_WAIT(n)   asm volatile("cp.async.wait_group %0;" ::"n"(n):"memory")

__device__ __forceinline__ void ldmx4(uint32_t* r, uint32_t addr) {
    asm volatile("ldmatrix.sync.aligned.m8n8.x4.shared.b16 {%0,%1,%2,%3}, [%4];"
        : "=r"(r[0]), "=r"(r[1]), "=r"(r[2]), "=r"(r[3]) : "r"(addr));
}
__device__ __forceinline__ void mma16816(float* c, const uint32_t* a,
                                         uint32_t b0, uint32_t b1) {
    asm volatile("mma.sync.aligned.m16n8k16.row.col.f32.bf16.bf16.f32 "
        "{%0,%1,%2,%3}, {%4,%5,%6,%7}, {%8,%9}, {%0,%1,%2,%3};"
        : "+f"(c[0]), "+f"(c[1]), "+f"(c[2]), "+f"(c[3])
        : "r"(a[0]), "r"(a[1]), "r"(a[2]), "r"(a[3]), "r"(b0), "r"(b1));
}

__device__ __forceinline__ void split2(float v, unsigned short& o0,
                                       unsigned short& o1) {
    __nv_bfloat16 b0 = __float2bfloat16_rn(v);
    float r = v - __bfloat162float(b0);
    __nv_bfloat16 b1 = __float2bfloat16_rn(r);
    o0 = *reinterpret_cast<unsigned short*>(&b0);
    o1 = *reinterpret_cast<unsigned short*>(&b1);
}

// ---------------- activation convert: [M,K] f32 -> [M,3K] planes [P0,P0,P1] ----------------
__global__ __launch_bounds__(256)
void convert_act(const float* __restrict__ src, __nv_bfloat16* __restrict__ dst,
                 int K, int total4)
{
    int i4 = blockIdx.x * 256 + threadIdx.x;
    if (i4 >= total4) return;
    long idx = (long)i4 * 4;
    int m = (int)(idx / K), k = (int)(idx % K);
    float4 v = *(const float4*)(src + idx);
    ushort4 p0, p1;
    split2(v.x, p0.x, p1.x);
    split2(v.y, p0.y, p1.y);
    split2(v.z, p0.z, p1.z);
    split2(v.w, p0.w, p1.w);
    long base = (long)m * (3L * K) + k;
    *(ushort4*)(dst + base)        = p0;
    *(ushort4*)(dst + base + K)    = p0;
    *(ushort4*)(dst + base + 2L*K) = p1;
}

// ---------------- weight convert+transpose: w[K,N] f32 -> [N,3K] planes [P0,P1,P0] ----------------
__global__ void convert_wT(const float* __restrict__ w, __nv_bfloat16* __restrict__ dst,
                           int K, int N)
{
    __shared__ float t[32][33];
    int n0 = blockIdx.x * 32, k0 = blockIdx.y * 32;
    int tx = threadIdx.x, ty = threadIdx.y;          // 32 x 8
#pragma unroll
    for (int r = 0; r < 4; r++)
        t[ty + r * 8][tx] = w[(long)(k0 + ty + r * 8) * N + n0 + tx];
    __syncthreads();
    unsigned short* d = (unsigned short*)dst;
#pragma unroll
    for (int r = 0; r < 4; r++) {
        int n = n0 + ty + r * 8;
        float v = t[tx][ty + r * 8];
        unsigned short b0, b1;
        split2(v, b0, b1);
        long base = (long)n * (3L * K) + k0 + tx;
        d[base]        = b0;
        d[base + K]    = b1;
        d[base + 2L*K] = b0;
    }
}

// ============ BIG GEMM: BM=256, BN=128, warp tile 64x64, BK=32, 3-stage ============
// EPI: 0=none, 2=gelu(+bias), 3=silu(aux)*acc, 4=+aux
template <int EPI>
__global__ __launch_bounds__(256, 1)
void bigmm(int Kp, const __nv_bfloat16* __restrict__ A,
           const __nv_bfloat16* __restrict__ Bt,
           float* __restrict__ C, int Nact,
           const float* __restrict__ bias, const float* __restrict__ aux)
{
    constexpr int RSTB = 80;                  // 64B data + 16B pad per row
    constexpr int ATILE = 256 * RSTB;         // 20480
    constexpr int BTILE = 128 * RSTB;         // 10240
    constexpr int STAGEB = ATILE + BTILE;     // 30720
    extern __shared__ char smc[];
    const uint32_t sb = smem_u32(smc);
    const int tid = threadIdx.x, lane = tid & 31, w = tid >> 5;
    const int wm = w >> 1, wn = w & 1;        // 4 x 2 warps, each 64x64
    const int bm = blockIdx.y * 256, bn = blockIdx.x * 128;

    const __nv_bfloat16* Ag = A + (long)bm * Kp;
    const __nv_bfloat16* Bg = Bt + (long)bn * Kp;
    const int KT = Kp / 32;

    float acc[4][8][4];
#pragma unroll
    for (int i = 0; i < 4; i++)
#pragma unroll
        for (int j = 0; j < 8; j++)
#pragma unroll
            for (int q = 0; q < 4; q++) acc[i][j][q] = 0.f;

    // load: A row = tid (4 segs), B row = tid>>1 (2 segs)
    const int bseg = (tid & 1) * 2;
    auto load_stage = [&](int s, int kt) {
        uint32_t as = sb + s * STAGEB;
        uint32_t bs = as + ATILE;
        long ko = (long)kt * 32;
#pragma unroll
        for (int i = 0; i < 4; i++)
            CPA16(as + tid * RSTB + i * 16, Ag + (long)tid * Kp + ko + i * 8);
#pragma unroll
        for (int i = 0; i < 2; i++)
            CPA16(bs + (tid >> 1) * RSTB + (bseg + i) * 16,
                  Bg + (long)(tid >> 1) * Kp + ko + (bseg + i) * 8);
        CPA_COMMIT();
    };

    load_stage(0, 0);
    if (KT > 1) load_stage(1, 1);

    const int arow = lane & 15;
    const int acol = (lane >> 4) * 16;

    for (int kt = 0; kt < KT; kt++) {
        if (kt + 2 < KT) { load_stage((kt + 2) % 3, kt + 2); CPA_WAIT(2); }
        else if (kt + 1 < KT) CPA_WAIT(1);
        else CPA_WAIT(0);
        __syncthreads();

        const uint32_t as = sb + (kt % 3) * STAGEB;
        const uint32_t bs = as + ATILE;
#pragma unroll
        for (int kk = 0; kk < 2; kk++) {
            const int co = kk * 32 + acol;
            uint32_t af[4][4], bf[4][4];
#pragma unroll
            for (int mi = 0; mi < 4; mi++)
                ldmx4(af[mi], as + (wm * 64 + mi * 16 + arow) * RSTB + co);
#pragma unroll
            for (int nj = 0; nj < 4; nj++)
                ldmx4(bf[nj], bs + (wn * 64 + nj * 16 + arow) * RSTB + co);
#pragma unroll
            for (int mi = 0; mi < 4; mi++)
#pragma unroll
                for (int ni = 0; ni < 8; ni++)
                    mma16816(acc[mi][ni], af[mi],
                             bf[ni >> 1][ni & 1], bf[ni >> 1][(ni & 1) + 2]);
        }
        __syncthreads();
    }

    // ---- epilogue ----
#pragma unroll
    for (int mi = 0; mi < 4; mi++) {
#pragma unroll
        for (int ni = 0; ni < 8; ni++) {
            int col = bn + wn * 64 + ni * 8 + (lane & 3) * 2;
            if (col >= Nact) continue;
#pragma unroll
            for (int h = 0; h < 2; h++) {
                long row = bm + wm * 64 + mi * 16 + (lane >> 2) + h * 8;
                float v0 = acc[mi][ni][h * 2 + 0];
                float v1 = acc[mi][ni][h * 2 + 1];
                if (EPI == 2) {
                    v0 += __ldg(bias + col); v1 += __ldg(bias + col + 1);
                    v0 = 0.5f * v0 * (1.0f + erff(v0 * 0.70710678118654752f));
                    v1 = 0.5f * v1 * (1.0f + erff(v1 * 0.70710678118654752f));
                } else if (EPI == 3) {
                    float2 s = *(const float2*)(aux + row * Nact + col);
                    v0 = (s.x / (1.0f + expf(-s.x))) * v0;
                    v1 = (s.y / (1.0f + expf(-s.y))) * v1;
                } else if (EPI == 4) {
                    float2 a = *(const float2*)(aux + row * Nact + col);
                    v0 += a.x; v1 += a.y;
                }
                *(float2*)(C + row * Nact + col) = make_float2(v0, v1);
            }
        }
    }
}

// ============ small GEMM (128x128, warp 64x32) — used for GEMM2 only ============
template <int EPI>
__global__ __launch_bounds__(256)
void mmagemm(int Kp, const __nv_bfloat16* __restrict__ A,
             const __nv_bfloat16* __restrict__ Bt,
             float* __restrict__ C, int Nact,
             const float* __restrict__ bias, const float* __restrict__ aux)
{
    constexpr int RSTB = 80;
    constexpr int TILEB = 128 * RSTB;
    constexpr int STAGEB = 2 * TILEB;
    extern __shared__ char smc[];
    const uint32_t sb = smem_u32(smc);
    const int tid = threadIdx.x, lane = tid & 31, w = tid >> 5;
    const int wm = w >> 2, wn = w & 3;
    const int bm = blockIdx.y * 128, bn = blockIdx.x * 128;

    const __nv_bfloat16* Ag = A + (long)bm * Kp;
    const __nv_bfloat16* Bg = Bt + (long)bn * Kp;
    const int lrow = tid >> 2;
    const int lseg = tid & 3;
    const int KT = Kp / 32;

    float acc[4][4][4];
#pragma unroll
    for (int i = 0; i < 4; i++)
#pragma unroll
        for (int j = 0; j < 4; j++)
#pragma unroll
            for (int q = 0; q < 4; q++) acc[i][j][q] = 0.f;

    auto load_stage = [&](int s, int kt) {
        uint32_t as = sb + s * STAGEB;
        uint32_t bs = as + TILEB;
        long ko = (long)kt * 32 + lseg * 8;
#pragma unroll
        for (int h = 0; h < 2; h++) {
            int r = lrow + h * 64;
            CPA16(as + r * RSTB + lseg * 16, Ag + (long)r * Kp + ko);
            CPA16(bs + r * RSTB + lseg * 16, Bg + (long)r * Kp + ko);
        }
        CPA_COMMIT();
    };

    load_stage(0, 0);
    if (KT > 1) load_stage(1, 1);

    const int arow = lane & 15;
    const int acol = (lane >> 4) * 16;

    for (int kt = 0; kt < KT; kt++) {
        if (kt + 2 < KT) { load_stage((kt + 2) % 3, kt + 2); CPA_WAIT(2); }
        else if (kt + 1 < KT) CPA_WAIT(1);
        else CPA_WAIT(0);
        __syncthreads();

        const uint32_t as = sb + (kt % 3) * STAGEB;
        const uint32_t bs = as + TILEB;
#pragma unroll
        for (int kk = 0; kk < 2; kk++) {
            const int co = kk * 32 + acol;
            uint32_t af[4][4], bf[2][4];
#pragma unroll
            for (int mi = 0; mi < 4; mi++)
                ldmx4(af[mi], as + (wm * 64 + mi * 16 + arow) * RSTB + co);
#pragma unroll
            for (int nj = 0; nj < 2; nj++)
                ldmx4(bf[nj], bs + (wn * 32 + nj * 16 + arow) * RSTB + co);
#pragma unroll
            for (int mi = 0; mi < 4; mi++)
#pragma unroll
                for (int ni = 0; ni < 4; ni++)
                    mma16816(acc[mi][ni], af[mi],
                             bf[ni >> 1][ni & 1], bf[ni >> 1][(ni & 1) + 2]);
        }
        __syncthreads();
    }

#pragma unroll
    for (int mi = 0; mi < 4; mi++) {
#pragma unroll
        for (int ni = 0; ni < 4; ni++) {
            int col = bn + wn * 32 + ni * 8 + (lane & 3) * 2;
            if (col >= Nact) continue;
#pragma unroll
            for (int h = 0; h < 2; h++) {
                long row = bm + wm * 64 + mi * 16 + (lane >> 2) + h * 8;
                float v0 = acc[mi][ni][h * 2 + 0];
                float v1 = acc[mi][ni][h * 2 + 1];
                if (EPI == 1) { v0 += __ldg(bias + col); v1 += __ldg(bias + col + 1); }
                *(float2*)(C + row * Nact + col) = make_float2(v0, v1);
            }
        }
    }
}

// ---------------- build gi = rmsnorm(concat(x, ctx, pos_emb)) ----------------
__global__ __launch_bounds__(256)
void build_gi_kernel(const float* __restrict__ x,
                     const int* __restrict__ positions,
                     const float* __restrict__ pos_table,
                     const float* __restrict__ normw)
{
    int row = blockIdx.x;
    __shared__ float vec[DGDIM];
    __shared__ float red[256];
    int tid = threadIdx.x;
    const float* xr = x + (long)row * HDIM;
    const float* pr = pos_table + (long)positions[row] * POSD;
    float ss = 0.f;
    for (int i = tid; i < DGDIM; i += 256) {
        float v;
        if (i < HDIM) v = xr[i];
        else if (i < HDIM + CTXD) v = g_ctx[(long)row * CTXD + (i - HDIM)];
        else v = pr[i - HDIM - CTXD];
        vec[i] = v;
        ss += v * v;
    }
    red[tid] = ss;
    __syncthreads();
    for (int s = 128; s > 0; s >>= 1) {
        if (tid < s) red[tid] += red[tid + s];
        __syncthreads();
    }
    float scale = rsqrtf(red[0] / (float)DGDIM + 1e-6f);
    for (int i = tid; i < DGDIM; i += 256)
        g_gi[(long)row * DGDIM + i] = vec[i] * scale * normw[i];
}

// ---------------- router ----------------
__global__ __launch_bounds__(256)
void router_kernel(const float* __restrict__ projw,
                   const float* __restrict__ tptr,
                   float* __restrict__ out)
{
    int row = blockIdx.x * 8 + (threadIdx.x >> 5);
    int lane = threadIdx.x & 31;
    if (row >= NTOK) return;
    const float* h = g_h + (long)row * DGDIM;
    float acc[NEXP];
#pragma unroll
    for (int e = 0; e < NEXP; e++) acc[e] = 0.f;
    for (int i = lane; i < DGDIM; i += 32) {
        float hv = h[i];
        const float4* p = (const float4*)(projw + (long)i * NEXP);
        float4 w0 = p[0], w1 = p[1];
        acc[0] += hv * w0.x; acc[1] += hv * w0.y;
        acc[2] += hv * w0.z; acc[3] += hv * w0.w;
        acc[4] += hv * w1.x; acc[5] += hv * w1.y;
        acc[6] += hv * w1.z; acc[7] += hv * w1.w;
    }
#pragma unroll
    for (int e = 0; e < NEXP; e++)
#pragma unroll
        for (int o = 16; o > 0; o >>= 1)
            acc[e] += __shfl_xor_sync(0xFFFFFFFFu, acc[e], o);

    if (lane == 0) {
        float t = fmaxf(*tptr, 0.3f);
        float l[NEXP], m = -1e30f;
#pragma unroll
        for (int e = 0; e < NEXP; e++) { l[e] = acc[e] / t; m = fmaxf(m, l[e]); }
        float s = 0.f;
#pragma unroll
        for (int e = 0; e < NEXP; e++) { l[e] = expf(l[e] - m); s += l[e]; }
        float inv = 1.0f / s;
#pragma unroll
        for (int e = 0; e < NEXP; e++) {
            l[e] *= inv;
            g_scores[(long)row * NEXP + e] = l[e];
        }
        int i1 = 0;
#pragma unroll
        for (int e = 1; e < NEXP; e++) if (l[e] > l[i1]) i1 = e;
        int i2 = (i1 == 0) ? 1 : 0;
#pragma unroll
        for (int e = 0; e < NEXP; e++)
            if (e != i1 && e != i2 && l[e] > l[i2]) i2 = e;

        int idx2[2] = {i1, i2};
#pragma unroll
        for (int k = 0; k < 2; k++) {
            int fi = row * 2 + k;
            float wv = l[idx2[k]];
            out[OFF_IDX + fi] = (float)idx2[k];
            out[OFF_SCORE + fi] = wv;
            g_expert_flat[fi] = idx2[k];
            unsigned int bits = __float_as_uint(wv);
            g_keys[fi] = ((unsigned long long)(0xFFFFFFFFu - bits) << 32) |
                         (unsigned long long)(unsigned int)fi;
        }
    }
}

// ---------------- single-block bitonic sort + capacity dispatch ----------------
__global__ __launch_bounds__(1024, 1)
void sort_dispatch_kernel(float* __restrict__ out)
{
    extern __shared__ unsigned long long keys[];
    const int tid = threadIdx.x;
    for (int i = tid; i < NKENT; i += 1024) keys[i] = g_keys[i];
    __syncthreads();
    for (int k = 2; k <= NKENT; k <<= 1) {
        for (int j = k >> 1; j > 0; j >>= 1) {
            for (int i = tid; i < NKENT; i += 1024) {
                int ixj = i ^ j;
                if (ixj > i) {
                    bool up = ((i & k) == 0);
                    unsigned long long a = keys[i], b = keys[ixj];
                    if ((a > b) == up) { keys[i] = b; keys[ixj] = a; }
                }
            }
            __syncthreads();
        }
    }
    int warp = tid >> 5, lane = tid & 31;
    if (warp < NEXP) {
        int c = 0;
        for (int base = 0; base < NKENT; base += 32) {
            unsigned long long kk = keys[base + lane];
            int idx = (int)(kk & 0xFFFFFFFFu);
            int e = g_expert_flat[idx];
            unsigned int mask = __ballot_sync(0xFFFFFFFFu, e == warp);
            if (e == warp) {
                int rank = c + __popc(mask & ((1u << lane) - 1u));
                bool ok = rank < CAP;
                g_assigned[idx] = ok ? 1 : 0;
                out[OFF_MASK + idx] = ok ? 1.0f : 0.0f;
                out[OFF_POS + idx] = ok ? (float)rank : 0.0f;
            }
            c += __popc(mask);
        }
        if (lane == 0) {
            int cnt = c < CAP ? c : CAP;
            g_cnt[warp] = cnt;
            out[OFF_CNT + warp] = (float)cnt;
        }
    }
    __syncthreads();
    for (int n = tid; n < NTOK; n += 1024)
        out[OFF_OVER + n] =
            (g_assigned[2 * n] | g_assigned[2 * n + 1]) ? 0.0f : 1.0f;
}

// ---------------- next_context mean ----------------
__global__ __launch_bounds__(256)
void next_ctx_kernel(const int* __restrict__ positions,
                     const float* __restrict__ pos_table,
                     float* __restrict__ out)
{
    int j = blockIdx.x % (CTXD + POSD);
    int b = blockIdx.x / (CTXD + POSD);
    __shared__ float red[256];
    float s = 0.f;
    for (int t = threadIdx.x; t < SEQ; t += 256) {
        int row = b * SEQ + t;
        float v = (j < CTXD) ? g_ctx[(long)row * CTXD + j]
                             : pos_table[(long)positions[row] * POSD + (j - CTXD)];
        s += v;
    }
    red[threadIdx.x] = s;
    __syncthreads();
    for (int st = 128; st > 0; st >>= 1) {
        if (threadIdx.x < st) red[threadIdx.x] += red[threadIdx.x + st];
        __syncthreads();
    }
    if (threadIdx.x == 0)
        out[OFF_NEXT + b * (CTXD + POSD) + j] = red[0] / (float)SEQ;
}

// ---------------- aux loss ----------------
__global__ __launch_bounds__(256)
void aux_kernel(float* __restrict__ out)
{
    __shared__ float sh[256 * NEXP];
    int tid = threadIdx.x;
    float acc[NEXP];
#pragma unroll
    for (int e = 0; e < NEXP; e++) acc[e] = 0.f;
    for (int r = tid; r < NTOK; r += 256)
#pragma unroll
        for (int e = 0; e < NEXP; e++) acc[e] += g_scores[(long)r * NEXP + e];
#pragma unroll
    for (int e = 0; e < NEXP; e++) sh[tid * NEXP + e] = acc[e];
    __syncthreads();
    for (int s = 128; s > 0; s >>= 1) {
        if (tid < s)
#pragma unroll
            for (int e = 0; e < NEXP; e++)
                sh[tid * NEXP + e] += sh[(tid + s) * NEXP + e];
        __syncthreads();
    }
    if (tid == 0) {
        float a = 0.f;
        for (int e = 0; e < NEXP; e++) {
            float me = sh[e] / (float)NTOK;
            float ce = (float)g_cnt[e] / (float)NTOK;
            a += me * ce;
        }
        out[OFF_AUX] = 0.01f * (float)NEXP * a;
    }
}

// ---------------- launch ----------------
extern "C" void kernel_launch(void* const* d_in, const int* in_sizes, int n_in,
                              void* d_out, int out_size)
{
    const float* x        = (const float*)d_in[0];
    const int*   positions= (const int*)d_in[1];
    const float* w_c1     = (const float*)d_in[2];
    const float* b_c1     = (const float*)d_in[3];
    const float* w_c2     = (const float*)d_in[4];
    const float* b_c2     = (const float*)d_in[5];
    const float* norm_w   = (const float*)d_in[6];
    const float* mlp_w1   = (const float*)d_in[7];
    const float* mlp_w3   = (const float*)d_in[8];
    const float* mlp_w2   = (const float*)d_in[9];
    const float* proj_w   = (const float*)d_in[10];
    const float* pos_table= (const float*)d_in[11];
    const float* temp     = (const float*)d_in[12];
    float* out = (float*)d_out;

    float *p_hidden, *p_ctx, *p_gi, *p_s1, *p_h1, *p_h;
    __nv_bfloat16 *p_ax, *p_ah, *p_agi, *p_ah1;
    __nv_bfloat16 *p_wc1t, *p_wc2t, *p_w1t, *p_w3t, *p_w2t;
    cudaGetSymbolAddress((void**)&p_hidden, g_hidden);
    cudaGetSymbolAddress((void**)&p_ctx,    g_ctx);
    cudaGetSymbolAddress((void**)&p_gi,     g_gi);
    cudaGetSymbolAddress((void**)&p_s1,     g_s1);
    cudaGetSymbolAddress((void**)&p_h1,     g_h1);
    cudaGetSymbolAddress((void**)&p_h,      g_h);
    cudaGetSymbolAddress((void**)&p_ax,     g_ax);
    cudaGetSymbolAddress((void**)&p_ah,     g_ah);
    cudaGetSymbolAddress((void**)&p_agi,    g_agi);
    cudaGetSymbolAddress((void**)&p_ah1,    g_ah1);
    cudaGetSymbolAddress((void**)&p_wc1t,   g_wc1t);
    cudaGetSymbolAddress((void**)&p_wc2t,   g_wc2t);
    cudaGetSymbolAddress((void**)&p_w1t,    g_w1t);
    cudaGetSymbolAddress((void**)&p_w3t,    g_w3t);
    cudaGetSymbolAddress((void**)&p_w2t,    g_w2t);

    const int GSM_S = 61440;   // small: 3 x 20480
    const int GSM_B = 92160;   // big:   3 x 30720
    cudaFuncSetAttribute(bigmm<0>, cudaFuncAttributeMaxDynamicSharedMemorySize, GSM_B);
    cudaFuncSetAttribute(bigmm<2>, cudaFuncAttributeMaxDynamicSharedMemorySize, GSM_B);
    cudaFuncSetAttribute(bigmm<3>, cudaFuncAttributeMaxDynamicSharedMemorySize, GSM_B);
    cudaFuncSetAttribute(bigmm<4>, cudaFuncAttributeMaxDynamicSharedMemorySize, GSM_B);
    cudaFuncSetAttribute(mmagemm<1>, cudaFuncAttributeMaxDynamicSharedMemorySize, GSM_S);
    cudaFuncSetAttribute(sort_dispatch_kernel,
                         cudaFuncAttributeMaxDynamicSharedMemorySize,
                         NKENT * (int)sizeof(unsigned long long));

    // zero padded weight buffers
    cudaMemsetAsync(p_wc2t, 0, (size_t)NPAD2 * KP2 * sizeof(__nv_bfloat16));
    cudaMemsetAsync(p_w2t,  0, (size_t)NPAD6 * KP6 * sizeof(__nv_bfloat16));

    // weight converts
    convert_wT<<<dim3(CH / 32, HDIM / 32),      dim3(32, 8)>>>(w_c1,   p_wc1t, HDIM,   CH);
    convert_wT<<<dim3(CTXD / 32, CH / 32),      dim3(32, 8)>>>(w_c2,   p_wc2t, CH,     CTXD);
    convert_wT<<<dim3(HIDDIM / 32, DGDIM / 32), dim3(32, 8)>>>(mlp_w1, p_w1t,  DGDIM,  HIDDIM);
    convert_wT<<<dim3(HIDDIM / 32, DGDIM / 32), dim3(32, 8)>>>(mlp_w3, p_w3t,  DGDIM,  HIDDIM);
    convert_wT<<<dim3(DGDIM / 32, HIDDIM / 32), dim3(32, 8)>>>(mlp_w2, p_w2t,  HIDDIM, DGDIM);
    // x split
    convert_act<<<(NTOK * HDIM / 4 + 255) / 256, 256>>>(x, p_ax, HDIM, NTOK * HDIM / 4);

    // 1. hidden = gelu(x @ w_c1 + b_c1)
    bigmm<2><<<dim3(CH / 128, NTOK / 256), 256, GSM_B>>>(
        KP1, p_ax, p_wc1t, p_hidden, CH, b_c1, nullptr);
    convert_act<<<(NTOK * CH / 4 + 255) / 256, 256>>>(p_hidden, p_ah, CH, NTOK * CH / 4);
    // 2. ctx = hidden @ w_c2 + b_c2   (small kernel, better fill at N=128)
    mmagemm<1><<<dim3(NPAD2 / 128, NTOK / 128), 256, GSM_S>>>(
        KP2, p_ah, p_wc2t, p_ctx, CTXD, b_c2, nullptr);
    // 3. gi = rmsnorm(concat(x, ctx, pos_emb))
    build_gi_kernel<<<NTOK, 256>>>(x, positions, pos_table, norm_w);
    convert_act<<<(NTOK * DGDIM / 4 + 255) / 256, 256>>>(p_gi, p_agi, DGDIM, NTOK * DGDIM / 4);
    // 4. s1 = gi @ mlp_w1
    bigmm<0><<<dim3(HIDDIM / 128, NTOK / 256), 256, GSM_B>>>(
        KP45, p_agi, p_w1t, p_s1, HIDDIM, nullptr, nullptr);
    // 5. h1 = silu(s1) * (gi @ mlp_w3)
    bigmm<3><<<dim3(HIDDIM / 128, NTOK / 256), 256, GSM_B>>>(
        KP45, p_agi, p_w3t, p_h1, HIDDIM, nullptr, p_s1);
    convert_act<<<(NTOK * HIDDIM / 4 + 255) / 256, 256>>>(p_h1, p_ah1, HIDDIM, NTOK * HIDDIM / 4);
    // 6. h = h1 @ mlp_w2 + gi
    bigmm<4><<<dim3(NPAD6 / 128, NTOK / 256), 256, GSM_B>>>(
        KP6, p_ah1, p_w2t, p_h, DGDIM, nullptr, p_gi);
    // 7-10. router, dispatch, next_context, aux
    router_kernel<<<NTOK / 8, 256>>>(proj_w, temp, out);
    sort_dispatch_kernel<<<1, 1024, NKENT * sizeof(unsigned long long)>>>(out);
    next_ctx_kernel<<<BATCH * (CTXD + POSD), 256>>>(positions, pos_table, out);
    aux_kernel<<<1, 256>>>(out);
}

// round 8
// speedup vs baseline: 1.4834x; 1.4834x over previous
#include <cuda_runtime.h>
#include <cuda_bf16.h>
#include <math.h>
#include <stdint.h>

// ---------------- static problem config ----------------
#define NTOK   8192
#define HDIM   1024
#define CH     2048
#define CTXD   64
#define POSD   32
#define DGDIM  1120
#define HIDDIM 3072
#define NEXP   8
#define NKENT  16384
#define CAP    2048
#define BATCH  4
#define SEQ    2048

// expanded-K (bf16x2 split, 3 products) widths
#define KP1   (3*HDIM)    // 3072  (div 64)
#define KP2   (3*CH)      // 6144  (div 64)
#define KP45  (3*DGDIM)   // 3360  actual data width
#define KP45P 3456        // padded to mult of 64 (pad stays zero)
#define KP6   (3*HIDDIM)  // 9216  (div 64)
#define NPAD2 128
#define NPAD6 1152

// output layout (flat float32, tuple order)
#define OFF_IDX   0
#define OFF_SCORE 16384
#define OFF_MASK  32768
#define OFF_POS   49152
#define OFF_OVER  65536
#define OFF_CNT   73728
#define OFF_AUX   73736
#define OFF_NEXT  73737

// ---------------- scratch (device globals, zero-initialized, no allocation) ----
__device__ float g_hidden[NTOK * CH];
__device__ float g_ctx[NTOK * CTXD];
__device__ float g_gi[NTOK * DGDIM];
__device__ float g_s1[NTOK * HIDDIM];
__device__ float g_h1[NTOK * HIDDIM];
__device__ float g_h[NTOK * DGDIM];
__device__ float g_scores[NTOK * NEXP];
__device__ unsigned long long g_keys[NKENT];
__device__ int g_expert_flat[NKENT];
__device__ unsigned char g_assigned[NKENT];
__device__ int g_cnt[NEXP];

__device__ __align__(256) __nv_bfloat16 g_ax  [NTOK * KP1];
__device__ __align__(256) __nv_bfloat16 g_ah  [NTOK * KP2];
__device__ __align__(256) __nv_bfloat16 g_agi [NTOK * KP45P];   // pad cols zero
__device__ __align__(256) __nv_bfloat16 g_ah1 [NTOK * KP6];
__device__ __align__(256) __nv_bfloat16 g_wc1t[CH    * KP1];
__device__ __align__(256) __nv_bfloat16 g_wc2t[NPAD2 * KP2];    // pad rows zero
__device__ __align__(256) __nv_bfloat16 g_w1t [HIDDIM* KP45P];  // pad cols zero
__device__ __align__(256) __nv_bfloat16 g_w3t [HIDDIM* KP45P];
__device__ __align__(256) __nv_bfloat16 g_w2t [NPAD6 * KP6];    // pad rows zero

// ---------------- helpers ----------------
__device__ __forceinline__ uint32_t smem_u32(const void* p) {
    uint32_t a;
    asm("{ .reg .u64 t; cvta.to.shared.u64 t, %1; cvt.u32.u64 %0, t; }"
        : "=r"(a) : "l"(p));
    return a;
}
#define CPA16(sa, gp) asm volatile("cp.async.cg.shared.global [%0], [%1], 16;" ::"r"(sa),"l"(gp):"memory")
#define CPA_COMMIT()  asm volatile("cp.async.commit_group;" ::: "memory")
#define CPA_WAIT(n)   asm volatile("cp.async.wait_group %0;" ::"n"(n):"memory")

__device__ __forceinline__ void ldmx4(uint32_t* r, uint32_t addr) {
    asm volatile("ldmatrix.sync.aligned.m8n8.x4.shared.b16 {%0,%1,%2,%3}, [%4];"
        : "=r"(r[0]), "=r"(r[1]), "=r"(r[2]), "=r"(r[3]) : "r"(addr));
}
__device__ __forceinline__ void mma16816(float* c, const uint32_t* a,
                                         uint32_t b0, uint32_t b1) {
    asm volatile("mma.sync.aligned.m16n8k16.row.col.f32.bf16.bf16.f32 "
        "{%0,%1,%2,%3}, {%4,%5,%6,%7}, {%8,%9}, {%0,%1,%2,%3};"
        : "+f"(c[0]), "+f"(c[1]), "+f"(c[2]), "+f"(c[3])
        : "r"(a[0]), "r"(a[1]), "r"(a[2]), "r"(a[3]), "r"(b0), "r"(b1));
}

__device__ __forceinline__ void split2(float v, unsigned short& o0,
                                       unsigned short& o1) {
    __nv_bfloat16 b0 = __float2bfloat16_rn(v);
    float r = v - __bfloat162float(b0);
    __nv_bfloat16 b1 = __float2bfloat16_rn(r);
    o0 = *reinterpret_cast<unsigned short*>(&b0);
    o1 = *reinterpret_cast<unsigned short*>(&b1);
}

// ------- activation convert: [M,K] f32 -> [M,KPAD] planes [P0,P0,P1] -------
__global__ __launch_bounds__(256)
void convert_act(const float* __restrict__ src, __nv_bfloat16* __restrict__ dst,
                 int K, int KPAD, int total4)
{
    int i4 = blockIdx.x * 256 + threadIdx.x;
    if (i4 >= total4) return;
    long idx = (long)i4 * 4;
    int m = (int)(idx / K), k = (int)(idx % K);
    float4 v = *(const float4*)(src + idx);
    ushort4 p0, p1;
    split2(v.x, p0.x, p1.x);
    split2(v.y, p0.y, p1.y);
    split2(v.z, p0.z, p1.z);
    split2(v.w, p0.w, p1.w);
    long base = (long)m * KPAD + k;
    *(ushort4*)(dst + base)        = p0;
    *(ushort4*)(dst + base + K)    = p0;
    *(ushort4*)(dst + base + 2L*K) = p1;
}

// ------- weight convert+transpose: w[K,N] f32 -> [N,KPAD] planes [P0,P1,P0] ----
__global__ void convert_wT(const float* __restrict__ w, __nv_bfloat16* __restrict__ dst,
                           int K, int N, int KPAD)
{
    __shared__ float t[32][33];
    int n0 = blockIdx.x * 32, k0 = blockIdx.y * 32;
    int tx = threadIdx.x, ty = threadIdx.y;          // 32 x 8
#pragma unroll
    for (int r = 0; r < 4; r++)
        t[ty + r * 8][tx] = w[(long)(k0 + ty + r * 8) * N + n0 + tx];
    __syncthreads();
    unsigned short* d = (unsigned short*)dst;
#pragma unroll
    for (int r = 0; r < 4; r++) {
        int n = n0 + ty + r * 8;
        float v = t[tx][ty + r * 8];
        unsigned short b0, b1;
        split2(v, b0, b1);
        long base = (long)n * KPAD + k0 + tx;
        d[base]        = b0;
        d[base + K]    = b1;
        d[base + 2L*K] = b0;
    }
}

// ===== GEMM: 128x128 CTA, warp 64x32, BK=64, 3-stage cp.async, 1 sync/iter =====
// EPI: 0=none, 1=+bias, 2=gelu(+bias), 3=silu(aux)*acc, 4=+aux
template <int EPI>
__global__ __launch_bounds__(256, 2)
void mmagemm(int Kp, const __nv_bfloat16* __restrict__ A,
             const __nv_bfloat16* __restrict__ Bt,
             float* __restrict__ C, int Nact,
             const float* __restrict__ bias, const float* __restrict__ aux)
{
    constexpr int RSTB = 144;                // 128B data + 16B pad per row
    constexpr int TILEB = 128 * RSTB;        // 18432 per operand
    constexpr int STAGEB = 2 * TILEB;        // 36864 per stage
    extern __shared__ char smc[];
    const uint32_t sb = smem_u32(smc);
    const int tid = threadIdx.x, lane = tid & 31, w = tid >> 5;
    const int wm = w >> 2, wn = w & 3;       // 2x4 warps, each 64x32
    const int bm = blockIdx.y * 128, bn = blockIdx.x * 128;

    const __nv_bfloat16* Ag = A + (long)bm * Kp;
    const __nv_bfloat16* Bg = Bt + (long)bn * Kp;
    const int KT = Kp / 64;

    float acc[4][4][4];
#pragma unroll
    for (int i = 0; i < 4; i++)
#pragma unroll
        for (int j = 0; j < 4; j++)
#pragma unroll
            for (int q = 0; q < 4; q++) acc[i][j][q] = 0.f;

    // load: 128 rows x 8 chunks(16B) per operand; 256 threads x 4 chunks each
    const int r0 = tid >> 3, sg = tid & 7;
    auto load_stage = [&](int s, int kt) {
        uint32_t as = sb + s * STAGEB;
        uint32_t bs = as + TILEB;
        long ko = (long)kt * 64 + sg * 8;
#pragma unroll
        for (int i = 0; i < 4; i++) {
            int r = r0 + i * 32;
            CPA16(as + r * RSTB + sg * 16, Ag + (long)r * Kp + ko);
            CPA16(bs + r * RSTB + sg * 16, Bg + (long)r * Kp + ko);
        }
        CPA_COMMIT();
    };

    load_stage(0, 0);
    if (KT > 1) load_stage(1, 1);

    const int arow = lane & 15;
    const int acol = (lane >> 4) * 16;

    for (int kt = 0; kt < KT; kt++) {
        if (kt + 1 < KT) CPA_WAIT(1);
        else CPA_WAIT(0);
        __syncthreads();                      // stage kt visible; all past kt-1
        if (kt + 2 < KT) load_stage((kt + 2) % 3, kt + 2);

        const uint32_t as = sb + (kt % 3) * STAGEB;
        const uint32_t bs = as + TILEB;
#pragma unroll
        for (int kk = 0; kk < 4; kk++) {
            const int co = kk * 32 + acol;
            uint32_t af[4][4], bf[2][4];
#pragma unroll
            for (int mi = 0; mi < 4; mi++)
                ldmx4(af[mi], as + (wm * 64 + mi * 16 + arow) * RSTB + co);
#pragma unroll
            for (int nj = 0; nj < 2; nj++)
                ldmx4(bf[nj], bs + (wn * 32 + nj * 16 + arow) * RSTB + co);
#pragma unroll
            for (int mi = 0; mi < 4; mi++)
#pragma unroll
                for (int ni = 0; ni < 4; ni++)
                    mma16816(acc[mi][ni], af[mi],
                             bf[ni >> 1][ni & 1], bf[ni >> 1][(ni & 1) + 2]);
        }
    }

    // ---- epilogue ----
#pragma unroll
    for (int mi = 0; mi < 4; mi++) {
#pragma unroll
        for (int ni = 0; ni < 4; ni++) {
            int col = bn + wn * 32 + ni * 8 + (lane & 3) * 2;
            if (col >= Nact) continue;
#pragma unroll
            for (int h = 0; h < 2; h++) {
                long row = bm + wm * 64 + mi * 16 + (lane >> 2) + h * 8;
                float v0 = acc[mi][ni][h * 2 + 0];
                float v1 = acc[mi][ni][h * 2 + 1];
                if (EPI == 1) { v0 += __ldg(bias + col); v1 += __ldg(bias + col + 1); }
                else if (EPI == 2) {
                    v0 += __ldg(bias + col); v1 += __ldg(bias + col + 1);
                    v0 = 0.5f * v0 * (1.0f + erff(v0 * 0.70710678118654752f));
                    v1 = 0.5f * v1 * (1.0f + erff(v1 * 0.70710678118654752f));
                } else if (EPI == 3) {
                    float2 s = *(const float2*)(aux + row * Nact + col);
                    v0 = (s.x / (1.0f + expf(-s.x))) * v0;
                    v1 = (s.y / (1.0f + expf(-s.y))) * v1;
                } else if (EPI == 4) {
                    float2 a = *(const float2*)(aux + row * Nact + col);
                    v0 += a.x; v1 += a.y;
                }
                *(float2*)(C + row * Nact + col) = make_float2(v0, v1);
            }
        }
    }
}

// ---------------- build gi = rmsnorm(concat(x, ctx, pos_emb)) ----------------
__global__ __launch_bounds__(256)
void build_gi_kernel(const float* __restrict__ x,
                     const int* __restrict__ positions,
                     const float* __restrict__ pos_table,
                     const float* __restrict__ normw)
{
    int row = blockIdx.x;
    __shared__ float vec[DGDIM];
    __shared__ float red[256];
    int tid = threadIdx.x;
    const float* xr = x + (long)row * HDIM;
    const float* pr = pos_table + (long)positions[row] * POSD;
    float ss = 0.f;
    for (int i = tid; i < DGDIM; i += 256) {
        float v;
        if (i < HDIM) v = xr[i];
        else if (i < HDIM + CTXD) v = g_ctx[(long)row * CTXD + (i - HDIM)];
        else v = pr[i - HDIM - CTXD];
        vec[i] = v;
        ss += v * v;
    }
    red[tid] = ss;
    __syncthreads();
    for (int s = 128; s > 0; s >>= 1) {
        if (tid < s) red[tid] += red[tid + s];
        __syncthreads();
    }
    float scale = rsqrtf(red[0] / (float)DGDIM + 1e-6f);
    for (int i = tid; i < DGDIM; i += 256)
        g_gi[(long)row * DGDIM + i] = vec[i] * scale * normw[i];
}

// ---------------- router ----------------
__global__ __launch_bounds__(256)
void router_kernel(const float* __restrict__ projw,
                   const float* __restrict__ tptr,
                   float* __restrict__ out)
{
    int row = blockIdx.x * 8 + (threadIdx.x >> 5);
    int lane = threadIdx.x & 31;
    if (row >= NTOK) return;
    const float* h = g_h + (long)row * DGDIM;
    float acc[NEXP];
#pragma unroll
    for (int e = 0; e < NEXP; e++) acc[e] = 0.f;
    for (int i = lane; i < DGDIM; i += 32) {
        float hv = h[i];
        const float4* p = (const float4*)(projw + (long)i * NEXP);
        float4 w0 = p[0], w1 = p[1];
        acc[0] += hv * w0.x; acc[1] += hv * w0.y;
        acc[2] += hv * w0.z; acc[3] += hv * w0.w;
        acc[4] += hv * w1.x; acc[5] += hv * w1.y;
        acc[6] += hv * w1.z; acc[7] += hv * w1.w;
    }
#pragma unroll
    for (int e = 0; e < NEXP; e++)
#pragma unroll
        for (int o = 16; o > 0; o >>= 1)
            acc[e] += __shfl_xor_sync(0xFFFFFFFFu, acc[e], o);

    if (lane == 0) {
        float t = fmaxf(*tptr, 0.3f);
        float l[NEXP], m = -1e30f;
#pragma unroll
        for (int e = 0; e < NEXP; e++) { l[e] = acc[e] / t; m = fmaxf(m, l[e]); }
        float s = 0.f;
#pragma unroll
        for (int e = 0; e < NEXP; e++) { l[e] = expf(l[e] - m); s += l[e]; }
        float inv = 1.0f / s;
#pragma unroll
        for (int e = 0; e < NEXP; e++) {
            l[e] *= inv;
            g_scores[(long)row * NEXP + e] = l[e];
        }
        int i1 = 0;
#pragma unroll
        for (int e = 1; e < NEXP; e++) if (l[e] > l[i1]) i1 = e;
        int i2 = (i1 == 0) ? 1 : 0;
#pragma unroll
        for (int e = 0; e < NEXP; e++)
            if (e != i1 && e != i2 && l[e] > l[i2]) i2 = e;

        int idx2[2] = {i1, i2};
#pragma unroll
        for (int k = 0; k < 2; k++) {
            int fi = row * 2 + k;
            float wv = l[idx2[k]];
            out[OFF_IDX + fi] = (float)idx2[k];
            out[OFF_SCORE + fi] = wv;
            g_expert_flat[fi] = idx2[k];
            unsigned int bits = __float_as_uint(wv);
            g_keys[fi] = ((unsigned long long)(0xFFFFFFFFu - bits) << 32) |
                         (unsigned long long)(unsigned int)fi;
        }
    }
}

// ---------------- single-block bitonic sort + capacity dispatch ----------------
__global__ __launch_bounds__(1024, 1)
void sort_dispatch_kernel(float* __restrict__ out)
{
    extern __shared__ unsigned long long keys[];
    const int tid = threadIdx.x;
    for (int i = tid; i < NKENT; i += 1024) keys[i] = g_keys[i];
    __syncthreads();
    for (int k = 2; k <= NKENT; k <<= 1) {
        for (int j = k >> 1; j > 0; j >>= 1) {
            for (int i = tid; i < NKENT; i += 1024) {
                int ixj = i ^ j;
                if (ixj > i) {
                    bool up = ((i & k) == 0);
                    unsigned long long a = keys[i], b = keys[ixj];
                    if ((a > b) == up) { keys[i] = b; keys[ixj] = a; }
                }
            }
            __syncthreads();
        }
    }
    int warp = tid >> 5, lane = tid & 31;
    if (warp < NEXP) {
        int c = 0;
        for (int base = 0; base < NKENT; base += 32) {
            unsigned long long kk = keys[base + lane];
            int idx = (int)(kk & 0xFFFFFFFFu);
            int e = g_expert_flat[idx];
            unsigned int mask = __ballot_sync(0xFFFFFFFFu, e == warp);
            if (e == warp) {
                int rank = c + __popc(mask & ((1u << lane) - 1u));
                bool ok = rank < CAP;
                g_assigned[idx] = ok ? 1 : 0;
                out[OFF_MASK + idx] = ok ? 1.0f : 0.0f;
                out[OFF_POS + idx] = ok ? (float)rank : 0.0f;
            }
            c += __popc(mask);
        }
        if (lane == 0) {
            int cnt = c < CAP ? c : CAP;
            g_cnt[warp] = cnt;
            out[OFF_CNT + warp] = (float)cnt;
        }
    }
    __syncthreads();
    for (int n = tid; n < NTOK; n += 1024)
        out[OFF_OVER + n] =
            (g_assigned[2 * n] | g_assigned[2 * n + 1]) ? 0.0f : 1.0f;
}

// ---------------- next_context mean ----------------
__global__ __launch_bounds__(256)
void next_ctx_kernel(const int* __restrict__ positions,
                     const float* __restrict__ pos_table,
                     float* __restrict__ out)
{
    int j = blockIdx.x % (CTXD + POSD);
    int b = blockIdx.x / (CTXD + POSD);
    __shared__ float red[256];
    float s = 0.f;
    for (int t = threadIdx.x; t < SEQ; t += 256) {
        int row = b * SEQ + t;
        float v = (j < CTXD) ? g_ctx[(long)row * CTXD + j]
                             : pos_table[(long)positions[row] * POSD + (j - CTXD)];
        s += v;
    }
    red[threadIdx.x] = s;
    __syncthreads();
    for (int st = 128; st > 0; st >>= 1) {
        if (threadIdx.x < st) red[threadIdx.x] += red[threadIdx.x + st];
        __syncthreads();
    }
    if (threadIdx.x == 0)
        out[OFF_NEXT + b * (CTXD + POSD) + j] = red[0] / (float)SEQ;
}

// ---------------- aux loss ----------------
__global__ __launch_bounds__(256)
void aux_kernel(float* __restrict__ out)
{
    __shared__ float sh[256 * NEXP];
    int tid = threadIdx.x;
    float acc[NEXP];
#pragma unroll
    for (int e = 0; e < NEXP; e++) acc[e] = 0.f;
    for (int r = tid; r < NTOK; r += 256)
#pragma unroll
        for (int e = 0; e < NEXP; e++) acc[e] += g_scores[(long)r * NEXP + e];
#pragma unroll
    for (int e = 0; e < NEXP; e++) sh[tid * NEXP + e] = acc[e];
    __syncthreads();
    for (int s = 128; s > 0; s >>= 1) {
        if (tid < s)
#pragma unroll
            for (int e = 0; e < NEXP; e++)
                sh[tid * NEXP + e] += sh[(tid + s) * NEXP + e];
        __syncthreads();
    }
    if (tid == 0) {
        float a = 0.f;
        for (int e = 0; e < NEXP; e++) {
            float me = sh[e] / (float)NTOK;
            float ce = (float)g_cnt[e] / (float)NTOK;
            a += me * ce;
        }
        out[OFF_AUX] = 0.01f * (float)NEXP * a;
    }
}

// ---------------- launch ----------------
extern "C" void kernel_launch(void* const* d_in, const int* in_sizes, int n_in,
                              void* d_out, int out_size)
{
    const float* x        = (const float*)d_in[0];
    const int*   positions= (const int*)d_in[1];
    const float* w_c1     = (const float*)d_in[2];
    const float* b_c1     = (const float*)d_in[3];
    const float* w_c2     = (const float*)d_in[4];
    const float* b_c2     = (const float*)d_in[5];
    const float* norm_w   = (const float*)d_in[6];
    const float* mlp_w1   = (const float*)d_in[7];
    const float* mlp_w3   = (const float*)d_in[8];
    const float* mlp_w2   = (const float*)d_in[9];
    const float* proj_w   = (const float*)d_in[10];
    const float* pos_table= (const float*)d_in[11];
    const float* temp     = (const float*)d_in[12];
    float* out = (float*)d_out;

    float *p_hidden, *p_ctx, *p_gi, *p_s1, *p_h1, *p_h;
    __nv_bfloat16 *p_ax, *p_ah, *p_agi, *p_ah1;
    __nv_bfloat16 *p_wc1t, *p_wc2t, *p_w1t, *p_w3t, *p_w2t;
    cudaGetSymbolAddress((void**)&p_hidden, g_hidden);
    cudaGetSymbolAddress((void**)&p_ctx,    g_ctx);
    cudaGetSymbolAddress((void**)&p_gi,     g_gi);
    cudaGetSymbolAddress((void**)&p_s1,     g_s1);
    cudaGetSymbolAddress((void**)&p_h1,     g_h1);
    cudaGetSymbolAddress((void**)&p_h,      g_h);
    cudaGetSymbolAddress((void**)&p_ax,     g_ax);
    cudaGetSymbolAddress((void**)&p_ah,     g_ah);
    cudaGetSymbolAddress((void**)&p_agi,    g_agi);
    cudaGetSymbolAddress((void**)&p_ah1,    g_ah1);
    cudaGetSymbolAddress((void**)&p_wc1t,   g_wc1t);
    cudaGetSymbolAddress((void**)&p_wc2t,   g_wc2t);
    cudaGetSymbolAddress((void**)&p_w1t,    g_w1t);
    cudaGetSymbolAddress((void**)&p_w3t,    g_w3t);
    cudaGetSymbolAddress((void**)&p_w2t,    g_w2t);

    const int GSM = 110592;   // 3 stages x 36864
    cudaFuncSetAttribute(mmagemm<0>, cudaFuncAttributeMaxDynamicSharedMemorySize, GSM);
    cudaFuncSetAttribute(mmagemm<1>, cudaFuncAttributeMaxDynamicSharedMemorySize, GSM);
    cudaFuncSetAttribute(mmagemm<2>, cudaFuncAttributeMaxDynamicSharedMemorySize, GSM);
    cudaFuncSetAttribute(mmagemm<3>, cudaFuncAttributeMaxDynamicSharedMemorySize, GSM);
    cudaFuncSetAttribute(mmagemm<4>, cudaFuncAttributeMaxDynamicSharedMemorySize, GSM);
    cudaFuncSetAttribute(sort_dispatch_kernel,
                         cudaFuncAttributeMaxDynamicSharedMemorySize,
                         NKENT * (int)sizeof(unsigned long long));

    // NOTE: pad regions of g_wc2t/g_w2t (N-pad rows) and g_agi/g_w1t/g_w3t
    // (K-pad cols) are never written; CUDA zero-init of __device__ globals
    // keeps them 0, so padded GEMM regions contribute nothing.

    // Launch order arranged so GEMM1 is launch #6 (ncu -s 5 -c 1 capture slot).
    // #1
    convert_wT<<<dim3(CH / 32, HDIM / 32),      dim3(32, 8)>>>(w_c1,   p_wc1t, HDIM,   CH,     KP1);
    // #2
    convert_act<<<(NTOK * HDIM / 4 + 255) / 256, 256>>>(x, p_ax, HDIM, KP1, NTOK * HDIM / 4);
    // #3
    convert_wT<<<dim3(CTXD / 32, CH / 32),      dim3(32, 8)>>>(w_c2,   p_wc2t, CH,     CTXD,   KP2);
    // #4
    convert_wT<<<dim3(HIDDIM / 32, DGDIM / 32), dim3(32, 8)>>>(mlp_w1, p_w1t,  DGDIM,  HIDDIM, KP45P);
    // #5
    convert_wT<<<dim3(HIDDIM / 32, DGDIM / 32), dim3(32, 8)>>>(mlp_w3, p_w3t,  DGDIM,  HIDDIM, KP45P);
    // #6: GEMM1 hidden = gelu(x @ w_c1 + b_c1)   <-- ncu capture slot
    mmagemm<2><<<dim3(CH / 128, NTOK / 128), 256, GSM>>>(
        KP1, p_ax, p_wc1t, p_hidden, CH, b_c1, nullptr);
    // remaining converts + GEMMs
    convert_act<<<(NTOK * CH / 4 + 255) / 256, 256>>>(p_hidden, p_ah, CH, KP2, NTOK * CH / 4);
    // GEMM2: ctx = hidden @ w_c2 + b_c2
    mmagemm<1><<<dim3(NPAD2 / 128, NTOK / 128), 256, GSM>>>(
        KP2, p_ah, p_wc2t, p_ctx, CTXD, b_c2, nullptr);
    // gi = rmsnorm(concat(x, ctx, pos_emb))
    build_gi_kernel<<<NTOK, 256>>>(x, positions, pos_table, norm_w);
    convert_act<<<(NTOK * DGDIM / 4 + 255) / 256, 256>>>(p_gi, p_agi, DGDIM, KP45P, NTOK * DGDIM / 4);
    // GEMM4: s1 = gi @ mlp_w1
    mmagemm<0><<<dim3(HIDDIM / 128, NTOK / 128), 256, GSM>>>(
        KP45P, p_agi, p_w1t, p_s1, HIDDIM, nullptr, nullptr);
    // GEMM5: h1 = silu(s1) * (gi @ mlp_w3)
    mmagemm<3><<<dim3(HIDDIM / 128, NTOK / 128), 256, GSM>>>(
        KP45P, p_agi, p_w3t, p_h1, HIDDIM, nullptr, p_s1);
    convert_act<<<(NTOK * HIDDIM / 4 + 255) / 256, 256>>>(p_h1, p_ah1, HIDDIM, KP6, NTOK * HIDDIM / 4);
    convert_wT<<<dim3(DGDIM / 32, HIDDIM / 32), dim3(32, 8)>>>(mlp_w2, p_w2t,  HIDDIM, DGDIM,  KP6);
    // GEMM6: h = h1 @ mlp_w2 + gi
    mmagemm<4><<<dim3(NPAD6 / 128, NTOK / 128), 256, GSM>>>(
        KP6, p_ah1, p_w2t, p_h, DGDIM, nullptr, p_gi);
    // router, dispatch, next_context, aux
    router_kernel<<<NTOK / 8, 256>>>(proj_w, temp, out);
    sort_dispatch_kernel<<<1, 1024, NKENT * sizeof(unsigned long long)>>>(out);
    next_ctx_kernel<<<BATCH * (CTXD + POSD), 256>>>(positions, pos_table, out);
    aux_kernel<<<1, 256>>>(out);
}

// round 9
// speedup vs baseline: 1.6814x; 1.1335x over previous
#include <cuda_runtime.h>
#include <cuda_bf16.h>
#include <math.h>
#include <stdint.h>

// ---------------- static problem config ----------------
#define NTOK   8192
#define HDIM   1024
#define CH     2048
#define CTXD   64
#define POSD   32
#define DGDIM  1120
#define HIDDIM 3072
#define NEXP   8
#define NKENT  16384
#define CAP    2048
#define BATCH  4
#define SEQ    2048

// expanded-K (bf16x2 split, 3 products) widths
#define KP1   (3*HDIM)    // 3072
#define KP2   (3*CH)      // 6144
#define KP45  (3*DGDIM)   // 3360
#define KP45P 3456        // padded to mult of 64 (pad stays zero)
#define KP6   (3*HIDDIM)  // 9216
#define NPAD2 128
#define NPAD6 1152

// output layout (flat float32, tuple order)
#define OFF_IDX   0
#define OFF_SCORE 16384
#define OFF_MASK  32768
#define OFF_POS   49152
#define OFF_OVER  65536
#define OFF_CNT   73728
#define OFF_AUX   73736
#define OFF_NEXT  73737

// ---------------- scratch (device globals, zero-initialized) ----------------
__device__ float g_ctx[NTOK * CTXD];
__device__ float g_gi[NTOK * DGDIM];
__device__ float g_s1[NTOK * HIDDIM];
__device__ float g_h[NTOK * DGDIM];
__device__ float g_scores[NTOK * NEXP];
__device__ unsigned long long g_keys[NKENT];
__device__ int g_expert_flat[NKENT];
__device__ unsigned char g_assigned[NKENT];
__device__ int g_cnt[NEXP];

__device__ __align__(256) __nv_bfloat16 g_ax  [NTOK * KP1];
__device__ __align__(256) __nv_bfloat16 g_ah  [NTOK * KP2];     // GEMM1 epi writes
__device__ __align__(256) __nv_bfloat16 g_agi [NTOK * KP45P];   // build_gi writes; pad 0
__device__ __align__(256) __nv_bfloat16 g_ah1 [NTOK * KP6];     // GEMM5 epi writes
__device__ __align__(256) __nv_bfloat16 g_wc1t[CH    * KP1];
__device__ __align__(256) __nv_bfloat16 g_wc2t[NPAD2 * KP2];    // pad rows zero
__device__ __align__(256) __nv_bfloat16 g_w1t [HIDDIM* KP45P];  // pad cols zero
__device__ __align__(256) __nv_bfloat16 g_w3t [HIDDIM* KP45P];
__device__ __align__(256) __nv_bfloat16 g_w2t [NPAD6 * KP6];    // pad rows zero

// ---------------- helpers ----------------
__device__ __forceinline__ uint32_t smem_u32(const void* p) {
    uint32_t a;
    asm("{ .reg .u64 t; cvta.to.shared.u64 t, %1; cvt.u32.u64 %0, t; }"
        : "=r"(a) : "l"(p));
    return a;
}
#define CPA16(sa, gp) asm volatile("cp.async.cg.shared.global [%0], [%1], 16;" ::"r"(sa),"l"(gp):"memory")
#define CPA_COMMIT()  asm volatile("cp.async.commit_group;" ::: "memory")
#define CPA_WAIT(n)   asm volatile("cp.async.wait_group %0;" ::"n"(n):"memory")

__device__ __forceinline__ void ldmx4(uint32_t* r, uint32_t addr) {
    asm volatile("ldmatrix.sync.aligned.m8n8.x4.shared.b16 {%0,%1,%2,%3}, [%4];"
        : "=r"(r[0]), "=r"(r[1]), "=r"(r[2]), "=r"(r[3]) : "r"(addr));
}
__device__ __forceinline__ void mma16816(float* c, const uint32_t* a,
                                         uint32_t b0, uint32_t b1) {
    asm volatile("mma.sync.aligned.m16n8k16.row.col.f32.bf16.bf16.f32 "
        "{%0,%1,%2,%3}, {%4,%5,%6,%7}, {%8,%9}, {%0,%1,%2,%3};"
        : "+f"(c[0]), "+f"(c[1]), "+f"(c[2]), "+f"(c[3])
        : "r"(a[0]), "r"(a[1]), "r"(a[2]), "r"(a[3]), "r"(b0), "r"(b1));
}

__device__ __forceinline__ void split2(float v, unsigned short& o0,
                                       unsigned short& o1) {
    __nv_bfloat16 b0 = __float2bfloat16_rn(v);
    float r = v - __bfloat162float(b0);
    __nv_bfloat16 b1 = __float2bfloat16_rn(r);
    o0 = *reinterpret_cast<unsigned short*>(&b0);
    o1 = *reinterpret_cast<unsigned short*>(&b1);
}

// ------- activation convert (x only): [M,K] f32 -> [M,KPAD] planes [P0,P0,P1] ---
__global__ __launch_bounds__(256)
void convert_act(const float* __restrict__ src, __nv_bfloat16* __restrict__ dst,
                 int K, int KPAD, int total4)
{
    int i4 = blockIdx.x * 256 + threadIdx.x;
    if (i4 >= total4) return;
    long idx = (long)i4 * 4;
    int m = (int)(idx / K), k = (int)(idx % K);
    float4 v = *(const float4*)(src + idx);
    ushort4 p0, p1;
    split2(v.x, p0.x, p1.x);
    split2(v.y, p0.y, p1.y);
    split2(v.z, p0.z, p1.z);
    split2(v.w, p0.w, p1.w);
    long base = (long)m * KPAD + k;
    *(ushort4*)(dst + base)        = p0;
    *(ushort4*)(dst + base + K)    = p0;
    *(ushort4*)(dst + base + 2L*K) = p1;
}

// ------- weight convert+transpose: w[K,N] f32 -> [N,KPAD] planes [P0,P1,P0] ----
__global__ void convert_wT(const float* __restrict__ w, __nv_bfloat16* __restrict__ dst,
                           int K, int N, int KPAD)
{
    __shared__ float t[32][33];
    int n0 = blockIdx.x * 32, k0 = blockIdx.y * 32;
    int tx = threadIdx.x, ty = threadIdx.y;          // 32 x 8
#pragma unroll
    for (int r = 0; r < 4; r++)
        t[ty + r * 8][tx] = w[(long)(k0 + ty + r * 8) * N + n0 + tx];
    __syncthreads();
    unsigned short* d = (unsigned short*)dst;
#pragma unroll
    for (int r = 0; r < 4; r++) {
        int n = n0 + ty + r * 8;
        float v = t[tx][ty + r * 8];
        unsigned short b0, b1;
        split2(v, b0, b1);
        long base = (long)n * KPAD + k0 + tx;
        d[base]        = b0;
        d[base + K]    = b1;
        d[base + 2L*K] = b0;
    }
}

// ===== GEMM: 128x128 CTA, warp 64x32, BK=64, 3-stage cp.async, 1 sync/iter =====
// EPI: 0=none(f32)  1=+bias(f32)  4=+aux(f32)
//      5=gelu(+bias)->planes      6=silu(aux)*acc->planes
template <int EPI>
__global__ __launch_bounds__(256, 2)
void mmagemm(int Kp, const __nv_bfloat16* __restrict__ A,
             const __nv_bfloat16* __restrict__ Bt,
             float* __restrict__ C, __nv_bfloat16* __restrict__ Cp, int Nact,
             const float* __restrict__ bias, const float* __restrict__ aux)
{
    constexpr int RSTB = 144;                // 128B data + 16B pad per row
    constexpr int TILEB = 128 * RSTB;        // 18432 per operand
    constexpr int STAGEB = 2 * TILEB;        // 36864 per stage
    extern __shared__ char smc[];
    const uint32_t sb = smem_u32(smc);
    const int tid = threadIdx.x, lane = tid & 31, w = tid >> 5;
    const int wm = w >> 2, wn = w & 3;       // 2x4 warps, each 64x32
    const int bm = blockIdx.y * 128, bn = blockIdx.x * 128;

    const __nv_bfloat16* Ag = A + (long)bm * Kp;
    const __nv_bfloat16* Bg = Bt + (long)bn * Kp;
    const int KT = Kp / 64;

    float acc[4][4][4];
#pragma unroll
    for (int i = 0; i < 4; i++)
#pragma unroll
        for (int j = 0; j < 4; j++)
#pragma unroll
            for (int q = 0; q < 4; q++) acc[i][j][q] = 0.f;

    const int r0 = tid >> 3, sg = tid & 7;
    auto load_stage = [&](int s, int kt) {
        uint32_t as = sb + s * STAGEB;
        uint32_t bs = as + TILEB;
        long ko = (long)kt * 64 + sg * 8;
#pragma unroll
        for (int i = 0; i < 4; i++) {
            int r = r0 + i * 32;
            CPA16(as + r * RSTB + sg * 16, Ag + (long)r * Kp + ko);
            CPA16(bs + r * RSTB + sg * 16, Bg + (long)r * Kp + ko);
        }
        CPA_COMMIT();
    };

    load_stage(0, 0);
    if (KT > 1) load_stage(1, 1);

    const int arow = lane & 15;
    const int acol = (lane >> 4) * 16;

    for (int kt = 0; kt < KT; kt++) {
        if (kt + 1 < KT) CPA_WAIT(1);
        else CPA_WAIT(0);
        __syncthreads();
        if (kt + 2 < KT) load_stage((kt + 2) % 3, kt + 2);

        const uint32_t as = sb + (kt % 3) * STAGEB;
        const uint32_t bs = as + TILEB;
#pragma unroll
        for (int kk = 0; kk < 4; kk++) {
            const int co = kk * 32 + acol;
            uint32_t af[4][4], bf[2][4];
#pragma unroll
            for (int mi = 0; mi < 4; mi++)
                ldmx4(af[mi], as + (wm * 64 + mi * 16 + arow) * RSTB + co);
#pragma unroll
            for (int nj = 0; nj < 2; nj++)
                ldmx4(bf[nj], bs + (wn * 32 + nj * 16 + arow) * RSTB + co);
#pragma unroll
            for (int mi = 0; mi < 4; mi++)
#pragma unroll
                for (int ni = 0; ni < 4; ni++)
                    mma16816(acc[mi][ni], af[mi],
                             bf[ni >> 1][ni & 1], bf[ni >> 1][(ni & 1) + 2]);
        }
    }

    // ---- epilogue ----
#pragma unroll
    for (int mi = 0; mi < 4; mi++) {
#pragma unroll
        for (int ni = 0; ni < 4; ni++) {
            int col = bn + wn * 32 + ni * 8 + (lane & 3) * 2;
            if (col >= Nact) continue;
#pragma unroll
            for (int h = 0; h < 2; h++) {
                long row = bm + wm * 64 + mi * 16 + (lane >> 2) + h * 8;
                float v0 = acc[mi][ni][h * 2 + 0];
                float v1 = acc[mi][ni][h * 2 + 1];
                if (EPI == 1) { v0 += __ldg(bias + col); v1 += __ldg(bias + col + 1); }
                else if (EPI == 5) {
                    v0 += __ldg(bias + col); v1 += __ldg(bias + col + 1);
                    v0 = 0.5f * v0 * (1.0f + erff(v0 * 0.70710678118654752f));
                    v1 = 0.5f * v1 * (1.0f + erff(v1 * 0.70710678118654752f));
                } else if (EPI == 6) {
                    float2 s = *(const float2*)(aux + row * Nact + col);
                    v0 = (s.x / (1.0f + expf(-s.x))) * v0;
                    v1 = (s.y / (1.0f + expf(-s.y))) * v1;
                } else if (EPI == 4) {
                    float2 a = *(const float2*)(aux + row * Nact + col);
                    v0 += a.x; v1 += a.y;
                }
                if (EPI == 5 || EPI == 6) {
                    // write bf16x2-split planes [P0,P0,P1], row stride 3*Nact
                    unsigned short a0, a1, c0, c1;
                    split2(v0, a0, a1);
                    split2(v1, c0, c1);
                    unsigned short* d = (unsigned short*)Cp;
                    long base = row * (3L * Nact) + col;
                    ushort2 p0 = make_ushort2(a0, c0);
                    ushort2 p1 = make_ushort2(a1, c1);
                    *(ushort2*)(d + base)            = p0;
                    *(ushort2*)(d + base + Nact)     = p0;
                    *(ushort2*)(d + base + 2L*Nact)  = p1;
                } else {
                    *(float2*)(C + row * Nact + col) = make_float2(v0, v1);
                }
            }
        }
    }
}

// ------- build gi = rmsnorm(concat(x, ctx, pos_emb)); also emit agi planes -----
__global__ __launch_bounds__(256)
void build_gi_kernel(const float* __restrict__ x,
                     const int* __restrict__ positions,
                     const float* __restrict__ pos_table,
                     const float* __restrict__ normw)
{
    int row = blockIdx.x;
    __shared__ float vec[DGDIM];
    __shared__ float red[256];
    int tid = threadIdx.x;
    const float* xr = x + (long)row * HDIM;
    const float* pr = pos_table + (long)positions[row] * POSD;
    float ss = 0.f;
    for (int i = tid; i < DGDIM; i += 256) {
        float v;
        if (i < HDIM) v = xr[i];
        else if (i < HDIM + CTXD) v = g_ctx[(long)row * CTXD + (i - HDIM)];
        else v = pr[i - HDIM - CTXD];
        vec[i] = v;
        ss += v * v;
    }
    red[tid] = ss;
    __syncthreads();
    for (int s = 128; s > 0; s >>= 1) {
        if (tid < s) red[tid] += red[tid + s];
        __syncthreads();
    }
    float scale = rsqrtf(red[0] / (float)DGDIM + 1e-6f);
    unsigned short* d = (unsigned short*)g_agi;
    for (int i = tid; i < DGDIM; i += 256) {
        float v = vec[i] * scale * normw[i];
        g_gi[(long)row * DGDIM + i] = v;
        unsigned short b0, b1;
        split2(v, b0, b1);
        long base = (long)row * KP45P + i;
        d[base]             = b0;
        d[base + DGDIM]     = b0;
        d[base + 2L*DGDIM]  = b1;
    }
}

// ---------------- router ----------------
__global__ __launch_bounds__(256)
void router_kernel(const float* __restrict__ projw,
                   const float* __restrict__ tptr,
                   float* __restrict__ out)
{
    int row = blockIdx.x * 8 + (threadIdx.x >> 5);
    int lane = threadIdx.x & 31;
    if (row >= NTOK) return;
    const float* h = g_h + (long)row * DGDIM;
    float acc[NEXP];
#pragma unroll
    for (int e = 0; e < NEXP; e++) acc[e] = 0.f;
    for (int i = lane; i < DGDIM; i += 32) {
        float hv = h[i];
        const float4* p = (const float4*)(projw + (long)i * NEXP);
        float4 w0 = p[0], w1 = p[1];
        acc[0] += hv * w0.x; acc[1] += hv * w0.y;
        acc[2] += hv * w0.z; acc[3] += hv * w0.w;
        acc[4] += hv * w1.x; acc[5] += hv * w1.y;
        acc[6] += hv * w1.z; acc[7] += hv * w1.w;
    }
#pragma unroll
    for (int e = 0; e < NEXP; e++)
#pragma unroll
        for (int o = 16; o > 0; o >>= 1)
            acc[e] += __shfl_xor_sync(0xFFFFFFFFu, acc[e], o);

    if (lane == 0) {
        float t = fmaxf(*tptr, 0.3f);
        float l[NEXP], m = -1e30f;
#pragma unroll
        for (int e = 0; e < NEXP; e++) { l[e] = acc[e] / t; m = fmaxf(m, l[e]); }
        float s = 0.f;
#pragma unroll
        for (int e = 0; e < NEXP; e++) { l[e] = expf(l[e] - m); s += l[e]; }
        float inv = 1.0f / s;
#pragma unroll
        for (int e = 0; e < NEXP; e++) {
            l[e] *= inv;
            g_scores[(long)row * NEXP + e] = l[e];
        }
        int i1 = 0;
#pragma unroll
        for (int e = 1; e < NEXP; e++) if (l[e] > l[i1]) i1 = e;
        int i2 = (i1 == 0) ? 1 : 0;
#pragma unroll
        for (int e = 0; e < NEXP; e++)
            if (e != i1 && e != i2 && l[e] > l[i2]) i2 = e;

        int idx2[2] = {i1, i2};
#pragma unroll
        for (int k = 0; k < 2; k++) {
            int fi = row * 2 + k;
            float wv = l[idx2[k]];
            out[OFF_IDX + fi] = (float)idx2[k];
            out[OFF_SCORE + fi] = wv;
            g_expert_flat[fi] = idx2[k];
            unsigned int bits = __float_as_uint(wv);
            g_keys[fi] = ((unsigned long long)(0xFFFFFFFFu - bits) << 32) |
                         (unsigned long long)(unsigned int)fi;
        }
    }
}

// -------- dispatch: one block per expert; gather -> bitonic -> rank ----------
// Per-expert rank under the global stable desc-weight sort == rank in an
// ascending sort of keys (~wbits, idx) restricted to that expert.
__global__ __launch_bounds__(1024, 1)
void dispatch_kernel(float* __restrict__ out)
{
    extern __shared__ unsigned long long sk[];   // up to NKENT keys (128 KB)
    __shared__ int s_cnt;
    const int e = blockIdx.x;
    const int tid = threadIdx.x;
    if (tid == 0) s_cnt = 0;
    __syncthreads();
    for (int i = tid; i < NKENT; i += 1024) {
        if (g_expert_flat[i] == e) {
            int p = atomicAdd(&s_cnt, 1);
            sk[p] = g_keys[i];
        }
    }
    __syncthreads();
    const int n = s_cnt;
    int P = 2;
    while (P < n) P <<= 1;
    for (int i = n + tid; i < P; i += 1024) sk[i] = 0xFFFFFFFFFFFFFFFFull;
    __syncthreads();
    for (int k = 2; k <= P; k <<= 1) {
        for (int j = k >> 1; j > 0; j >>= 1) {
            for (int i = tid; i < P; i += 1024) {
                int ixj = i ^ j;
                if (ixj > i) {
                    bool up = ((i & k) == 0);
                    unsigned long long a = sk[i], b = sk[ixj];
                    if ((a > b) == up) { sk[i] = b; sk[ixj] = a; }
                }
            }
            __syncthreads();
        }
    }
    for (int p = tid; p < n; p += 1024) {
        int idx = (int)(sk[p] & 0xFFFFFFFFu);
        bool ok = p < CAP;
        g_assigned[idx] = ok ? 1 : 0;
        out[OFF_MASK + idx] = ok ? 1.0f : 0.0f;
        out[OFF_POS + idx] = ok ? (float)p : 0.0f;
    }
    if (tid == 0) {
        int cnt = n < CAP ? n : CAP;
        g_cnt[e] = cnt;
        out[OFF_CNT + e] = (float)cnt;
    }
}

__global__ __launch_bounds__(256)
void overflow_kernel(float* __restrict__ out)
{
    int n = blockIdx.x * 256 + threadIdx.x;
    if (n < NTOK)
        out[OFF_OVER + n] =
            (g_assigned[2 * n] | g_assigned[2 * n + 1]) ? 0.0f : 1.0f;
}

// ---------------- next_context mean ----------------
__global__ __launch_bounds__(256)
void next_ctx_kernel(const int* __restrict__ positions,
                     const float* __restrict__ pos_table,
                     float* __restrict__ out)
{
    int j = blockIdx.x % (CTXD + POSD);
    int b = blockIdx.x / (CTXD + POSD);
    __shared__ float red[256];
    float s = 0.f;
    for (int t = threadIdx.x; t < SEQ; t += 256) {
        int row = b * SEQ + t;
        float v = (j < CTXD) ? g_ctx[(long)row * CTXD + j]
                             : pos_table[(long)positions[row] * POSD + (j - CTXD)];
        s += v;
    }
    red[threadIdx.x] = s;
    __syncthreads();
    for (int st = 128; st > 0; st >>= 1) {
        if (threadIdx.x < st) red[threadIdx.x] += red[threadIdx.x + st];
        __syncthreads();
    }
    if (threadIdx.x == 0)
        out[OFF_NEXT + b * (CTXD + POSD) + j] = red[0] / (float)SEQ;
}

// ---------------- aux loss ----------------
__global__ __launch_bounds__(256)
void aux_kernel(float* __restrict__ out)
{
    __shared__ float sh[256 * NEXP];
    int tid = threadIdx.x;
    float acc[NEXP];
#pragma unroll
    for (int e = 0; e < NEXP; e++) acc[e] = 0.f;
    for (int r = tid; r < NTOK; r += 256)
#pragma unroll
        for (int e = 0; e < NEXP; e++) acc[e] += g_scores[(long)r * NEXP + e];
#pragma unroll
    for (int e = 0; e < NEXP; e++) sh[tid * NEXP + e] = acc[e];
    __syncthreads();
    for (int s = 128; s > 0; s >>= 1) {
        if (tid < s)
#pragma unroll
            for (int e = 0; e < NEXP; e++)
                sh[tid * NEXP + e] += sh[(tid + s) * NEXP + e];
        __syncthreads();
    }
    if (tid == 0) {
        float a = 0.f;
        for (int e = 0; e < NEXP; e++) {
            float me = sh[e] / (float)NTOK;
            float ce = (float)g_cnt[e] / (float)NTOK;
            a += me * ce;
        }
        out[OFF_AUX] = 0.01f * (float)NEXP * a;
    }
}

// ---------------- launch ----------------
extern "C" void kernel_launch(void* const* d_in, const int* in_sizes, int n_in,
                              void* d_out, int out_size)
{
    const float* x        = (const float*)d_in[0];
    const int*   positions= (const int*)d_in[1];
    const float* w_c1     = (const float*)d_in[2];
    const float* b_c1     = (const float*)d_in[3];
    const float* w_c2     = (const float*)d_in[4];
    const float* b_c2     = (const float*)d_in[5];
    const float* norm_w   = (const float*)d_in[6];
    const float* mlp_w1   = (const float*)d_in[7];
    const float* mlp_w3   = (const float*)d_in[8];
    const float* mlp_w2   = (const float*)d_in[9];
    const float* proj_w   = (const float*)d_in[10];
    const float* pos_table= (const float*)d_in[11];
    const float* temp     = (const float*)d_in[12];
    float* out = (float*)d_out;

    float *p_ctx, *p_gi, *p_s1, *p_h;
    __nv_bfloat16 *p_ax, *p_ah, *p_agi, *p_ah1;
    __nv_bfloat16 *p_wc1t, *p_wc2t, *p_w1t, *p_w3t, *p_w2t;
    cudaGetSymbolAddress((void**)&p_ctx,    g_ctx);
    cudaGetSymbolAddress((void**)&p_gi,     g_gi);
    cudaGetSymbolAddress((void**)&p_s1,     g_s1);
    cudaGetSymbolAddress((void**)&p_h,      g_h);
    cudaGetSymbolAddress((void**)&p_ax,     g_ax);
    cudaGetSymbolAddress((void**)&p_ah,     g_ah);
    cudaGetSymbolAddress((void**)&p_agi,    g_agi);
    cudaGetSymbolAddress((void**)&p_ah1,    g_ah1);
    cudaGetSymbolAddress((void**)&p_wc1t,   g_wc1t);
    cudaGetSymbolAddress((void**)&p_wc2t,   g_wc2t);
    cudaGetSymbolAddress((void**)&p_w1t,    g_w1t);
    cudaGetSymbolAddress((void**)&p_w3t,    g_w3t);
    cudaGetSymbolAddress((void**)&p_w2t,    g_w2t);

    const int GSM = 110592;   // 3 stages x 36864
    cudaFuncSetAttribute(mmagemm<0>, cudaFuncAttributeMaxDynamicSharedMemorySize, GSM);
    cudaFuncSetAttribute(mmagemm<1>, cudaFuncAttributeMaxDynamicSharedMemorySize, GSM);
    cudaFuncSetAttribute(mmagemm<4>, cudaFuncAttributeMaxDynamicSharedMemorySize, GSM);
    cudaFuncSetAttribute(mmagemm<5>, cudaFuncAttributeMaxDynamicSharedMemorySize, GSM);
    cudaFuncSetAttribute(mmagemm<6>, cudaFuncAttributeMaxDynamicSharedMemorySize, GSM);
    cudaFuncSetAttribute(dispatch_kernel,
                         cudaFuncAttributeMaxDynamicSharedMemorySize,
                         NKENT * (int)sizeof(unsigned long long));

    // #1..#4: converts (deps for GEMM1/2)
    convert_wT<<<dim3(CH / 32, HDIM / 32),      dim3(32, 8)>>>(w_c1,   p_wc1t, HDIM,   CH,     KP1);
    convert_wT<<<dim3(CTXD / 32, CH / 32),      dim3(32, 8)>>>(w_c2,   p_wc2t, CH,     CTXD,   KP2);
    convert_act<<<(NTOK * HDIM / 4 + 255) / 256, 256>>>(x, p_ax, HDIM, KP1, NTOK * HDIM / 4);
    convert_wT<<<dim3(HIDDIM / 32, DGDIM / 32), dim3(32, 8)>>>(mlp_w1, p_w1t,  DGDIM,  HIDDIM, KP45P);
    // #5: GEMM1 gelu(x@w_c1+b_c1) -> g_ah planes   <-- ncu capture candidates
    mmagemm<5><<<dim3(CH / 128, NTOK / 128), 256, GSM>>>(
        KP1, p_ax, p_wc1t, nullptr, p_ah, CH, b_c1, nullptr);
    // #6: GEMM2 ctx = hidden @ w_c2 + b_c2 (f32)
    mmagemm<1><<<dim3(NPAD2 / 128, NTOK / 128), 256, GSM>>>(
        KP2, p_ah, p_wc2t, p_ctx, nullptr, CTXD, b_c2, nullptr);
    // #7
    convert_wT<<<dim3(HIDDIM / 32, DGDIM / 32), dim3(32, 8)>>>(mlp_w3, p_w3t,  DGDIM,  HIDDIM, KP45P);
    // #8: gi = rmsnorm(concat(...)), also emits agi planes
    build_gi_kernel<<<NTOK, 256>>>(x, positions, pos_table, norm_w);
    // #9: GEMM4 s1 = gi @ mlp_w1 (f32)
    mmagemm<0><<<dim3(HIDDIM / 128, NTOK / 128), 256, GSM>>>(
        KP45P, p_agi, p_w1t, p_s1, nullptr, HIDDIM, nullptr, nullptr);
    // #10: GEMM5 h1 = silu(s1) * (gi @ mlp_w3) -> g_ah1 planes
    mmagemm<6><<<dim3(HIDDIM / 128, NTOK / 128), 256, GSM>>>(
        KP45P, p_agi, p_w3t, nullptr, p_ah1, HIDDIM, nullptr, p_s1);
    // #11
    convert_wT<<<dim3(DGDIM / 32, HIDDIM / 32), dim3(32, 8)>>>(mlp_w2, p_w2t,  HIDDIM, DGDIM,  KP6);
    // #12: GEMM6 h = h1 @ mlp_w2 + gi (f32)
    mmagemm<4><<<dim3(NPAD6 / 128, NTOK / 128), 256, GSM>>>(
        KP6, p_ah1, p_w2t, p_h, nullptr, DGDIM, nullptr, p_gi);
    // router, dispatch (8 per-expert blocks), overflow, next_context, aux
    router_kernel<<<NTOK / 8, 256>>>(proj_w, temp, out);
    dispatch_kernel<<<NEXP, 1024, NKENT * sizeof(unsigned long long)>>>(out);
    overflow_kernel<<<NTOK / 256, 256>>>(out);
    next_ctx_kernel<<<BATCH * (CTXD + POSD), 256>>>(positions, pos_table, out);
    aux_kernel<<<1, 256>>>(out);
}